// round 1
// baseline (speedup 1.0000x reference)
#include <cuda_runtime.h>
#include <cuda_bf16.h>
#include <math.h>

// Problem shapes (fixed per reference)
#define N_NODES 20000
#define N_EDGES 40000
#define H 64
#define F_ATOM 62
#define F_BOND 6
#define BGRAPH 512
#define HH 4096  // H*H

// ---------------- scratch (device globals; no allocs allowed) ----------------
__device__ float g_h[N_NODES * H];        // node state
__device__ float g_msg[N_NODES * H];      // per-step message accumulator
__device__ float g_act[N_NODES * H];      // atom activation
__device__ float g_mlp[N_EDGES * H];      // edge MLP features
__device__ float g_EwT[H * HH];           // permuted Ew: EwT[m, j*H+i] = Ew[m, i*H+j]
__device__ float g_A[(size_t)N_EDGES * HH]; // per-edge matrices, TRANSPOSED layout At[e, j*H+i]
__device__ float g_gsum[BGRAPH * H];      // graph segment sums

// ---------------- helpers ----------------
__device__ __forceinline__ float selu_f(float x) {
    const float alpha = 1.6732632423543772f;
    const float scale = 1.0507009873554805f;
    return x > 0.f ? scale * x : scale * alpha * expm1f(x);
}

__global__ void k_zero(float* p, int n) {
    int i = blockIdx.x * blockDim.x + threadIdx.x;
    if (i < n) p[i] = 0.f;
}

// pad node features [N, F_ATOM] -> g_h [N, H] (zero-pad tail)
__global__ void k_pad(const float* __restrict__ nf) {
    int idx = blockIdx.x * blockDim.x + threadIdx.x;
    if (idx >= N_NODES * H) return;
    int n = idx >> 6, c = idx & 63;
    g_h[idx] = (c < F_ATOM) ? nf[n * F_ATOM + c] : 0.f;
}

// mlp = relu(ef @ Wm + bm)  : 4 edges per block of 256
__global__ void k_mlp(const float* __restrict__ ef, const float* __restrict__ Wm,
                      const float* __restrict__ bm) {
    __shared__ float s_ef[4][F_BOND];
    int tid = threadIdx.x;
    int sub = tid >> 6, i = tid & 63;
    int e = blockIdx.x * 4 + sub;
    if (i < F_BOND) s_ef[sub][i] = ef[e * F_BOND + i];
    __syncthreads();
    float v = bm[i];
#pragma unroll
    for (int f = 0; f < F_BOND; f++) v += s_ef[sub][f] * Wm[f * H + i];
    g_mlp[e * H + i] = fmaxf(v, 0.f);
}

// EwT[m, j*64+i] = Ew[m, i*64+j]
__global__ void k_permuteEw(const float* __restrict__ Ew) {
    int o = blockIdx.x * blockDim.x + threadIdx.x;
    if (o >= H * HH) return;
    int m = o >> 12, c = o & 4095;
    int j = c >> 6, i = c & 63;
    g_EwT[o] = Ew[(m << 12) + (i << 6) + j];
}

// A = mlp[E,64] @ EwT[64,4096]  -> g_A  (64x64 output tile per block, 256 threads, 4x4/thread)
__global__ void __launch_bounds__(256) k_gemmA() {
    __shared__ float As[64][65]; // As[k][m], padded: conflict-free stores
    __shared__ float Bs[64][64]; // Bs[k][n]
    int tid = threadIdx.x;
    int m0 = blockIdx.y * 64;
    int n0 = blockIdx.x * 64;
    int lr = tid >> 6;        // 0..3
    int lc = tid & 63;        // 0..63
#pragma unroll
    for (int r = 0; r < 64; r += 4)
        As[lc][r + lr] = g_mlp[(m0 + r + lr) * H + lc];
#pragma unroll
    for (int r = 0; r < 64; r += 4)
        Bs[r + lr][lc] = g_EwT[(r + lr) * HH + n0 + lc];
    __syncthreads();
    int tx = tid & 15, ty = tid >> 4; // 16x16 thread grid
    float acc[4][4] = {};
#pragma unroll
    for (int k = 0; k < 64; k++) {
        float a[4], b[4];
#pragma unroll
        for (int u = 0; u < 4; u++) a[u] = As[k][ty * 4 + u];
        float4 b4 = *(const float4*)&Bs[k][tx * 4];
        b[0] = b4.x; b[1] = b4.y; b[2] = b4.z; b[3] = b4.w;
#pragma unroll
        for (int u = 0; u < 4; u++)
#pragma unroll
            for (int v = 0; v < 4; v++) acc[u][v] = fmaf(a[u], b[v], acc[u][v]);
    }
#pragma unroll
    for (int u = 0; u < 4; u++) {
        float4 o = make_float4(acc[u][0], acc[u][1], acc[u][2], acc[u][3]);
        *(float4*)&g_A[(size_t)(m0 + ty * 4 + u) * HH + n0 + tx * 4] = o;
    }
}

// edge pass: em[e,i] = sum_j At[e, j*64+i] * h[rng[e], j];  atomicAdd into msg[dom[e], i]
__global__ void __launch_bounds__(256) k_edge(const int* __restrict__ dom,
                                              const int* __restrict__ rng) {
    __shared__ float s_hj[4][64];
    int tid = threadIdx.x;
    int sub = tid >> 6, i = tid & 63;
    int e = blockIdx.x * 4 + sub;
    int r = rng[e];
    s_hj[sub][i] = g_h[r * H + i];
    __syncthreads();
    const float* Ae = g_A + (size_t)e * HH;
    float acc = 0.f;
#pragma unroll 8
    for (int j = 0; j < 64; j++)
        acc = fmaf(__ldg(&Ae[j * 64 + i]), s_hj[sub][j], acc);
    atomicAdd(&g_msg[dom[e] * H + i], acc);
}

// h = selu(msg @ Wu + bu + h)   : 4 nodes per block
__global__ void k_update(const float* __restrict__ Wu, const float* __restrict__ bu) {
    __shared__ float s_m[4][64];
    int tid = threadIdx.x;
    int sub = tid >> 6, i = tid & 63;
    int n = blockIdx.x * 4 + sub;
    s_m[sub][i] = g_msg[n * H + i];
    __syncthreads();
    float acc = bu[i];
#pragma unroll 8
    for (int k = 0; k < 64; k++) acc = fmaf(s_m[sub][k], Wu[k * H + i], acc);
    int idx = n * H + i;
    g_h[idx] = selu_f(acc + g_h[idx]);
}

// act = selu((h @ Wae + bae) @ WR + bR)   : 4 nodes per block
__global__ void k_embed(const float* __restrict__ Wae, const float* __restrict__ bae,
                        const float* __restrict__ WR, const float* __restrict__ bR) {
    __shared__ float s_h[4][64];
    __shared__ float s_ae[4][64];
    int tid = threadIdx.x;
    int sub = tid >> 6, i = tid & 63;
    int n = blockIdx.x * 4 + sub;
    s_h[sub][i] = g_h[n * H + i];
    __syncthreads();
    float ae = bae[i];
#pragma unroll 8
    for (int k = 0; k < 64; k++) ae = fmaf(s_h[sub][k], Wae[k * H + i], ae);
    s_ae[sub][i] = ae;
    __syncthreads();
    float acc = bR[i];
#pragma unroll 8
    for (int k = 0; k < 64; k++) acc = fmaf(s_ae[sub][k], WR[k * H + i], acc);
    g_act[n * H + i] = selu_f(acc);
}

// segment-sum act over graph_id
__global__ void k_graphsum(const int* __restrict__ gid) {
    int idx = blockIdx.x * blockDim.x + threadIdx.x;
    if (idx >= N_NODES * H) return;
    int n = idx >> 6, i = idx & 63;
    atomicAdd(&g_gsum[gid[n] * H + i], g_act[idx]);
}

// out[b] = relu(tanh(gsum[b]) @ Wmlp + bmlp) @ Wout + bout
__global__ void k_readout(const float* __restrict__ Wmlp, const float* __restrict__ bmlp,
                          const float* __restrict__ Wout, const float* __restrict__ bout,
                          float* __restrict__ out) {
    __shared__ float s_ge[64];
    __shared__ float s_red[64];
    int b = blockIdx.x, i = threadIdx.x;
    s_ge[i] = tanhf(g_gsum[b * H + i]);
    __syncthreads();
    float acc = bmlp[i];
#pragma unroll 8
    for (int k = 0; k < 64; k++) acc = fmaf(s_ge[k], Wmlp[k * H + i], acc);
    float p = fmaxf(acc, 0.f) * Wout[i];
    s_red[i] = p;
    __syncthreads();
#pragma unroll
    for (int s = 32; s > 0; s >>= 1) {
        if (i < s) s_red[i] += s_red[i + s];
        __syncthreads();
    }
    if (i == 0) out[b] = s_red[0] + bout[0];
}

extern "C" void kernel_launch(void* const* d_in, const int* in_sizes, int n_in,
                              void* d_out, int out_size) {
    const float* node_features = (const float*)d_in[0];
    const float* edge_features = (const float*)d_in[1];
    const int*   edge_domain   = (const int*)d_in[2];
    const int*   edge_range    = (const int*)d_in[3];
    const int*   graph_id      = (const int*)d_in[4];
    const float* Wm   = (const float*)d_in[5];
    const float* bm   = (const float*)d_in[6];
    const float* Ew   = (const float*)d_in[7];
    const float* Wu0  = (const float*)d_in[8];
    const float* bu0  = (const float*)d_in[9];
    const float* Wu1  = (const float*)d_in[10];
    const float* bu1  = (const float*)d_in[11];
    const float* Wae  = (const float*)d_in[12];
    const float* bae  = (const float*)d_in[13];
    const float* WR   = (const float*)d_in[14];
    const float* bR   = (const float*)d_in[15];
    const float* Wmlp = (const float*)d_in[16];
    const float* bmlp = (const float*)d_in[17];
    const float* Wout = (const float*)d_in[18];
    const float* bout = (const float*)d_in[19];
    float* out = (float*)d_out;

    // prep
    k_pad<<<(N_NODES * H + 255) / 256, 256>>>(node_features);
    k_mlp<<<N_EDGES / 4, 256>>>(edge_features, Wm, bm);
    k_permuteEw<<<(H * HH + 255) / 256, 256>>>(Ew);

    // A = mlp @ EwT (stored transposed per edge)
    dim3 gA(HH / 64, N_EDGES / 64);
    k_gemmA<<<gA, 256>>>();

    // message passing steps
    const float* Wus[2] = {Wu0, Wu1};
    const float* bus[2] = {bu0, bu1};
    float* msg_ptr = nullptr;
    cudaGetSymbolAddress((void**)&msg_ptr, g_msg);
    float* gsum_ptr = nullptr;
    cudaGetSymbolAddress((void**)&gsum_ptr, g_gsum);

    for (int t = 0; t < 2; t++) {
        k_zero<<<(N_NODES * H + 255) / 256, 256>>>(msg_ptr, N_NODES * H);
        k_edge<<<N_EDGES / 4, 256>>>(edge_domain, edge_range);
        k_update<<<N_NODES / 4, 256>>>(Wus[t], bus[t]);
    }

    // readout
    k_embed<<<N_NODES / 4, 256>>>(Wae, bae, WR, bR);
    k_zero<<<(BGRAPH * H + 255) / 256, 256>>>(gsum_ptr, BGRAPH * H);
    k_graphsum<<<(N_NODES * H + 255) / 256, 256>>>(graph_id);
    k_readout<<<BGRAPH, 64>>>(Wmlp, bmlp, Wout, bout, out);
}

// round 4
// speedup vs baseline: 2.2173x; 2.2173x over previous
#include <cuda_runtime.h>
#include <cuda_bf16.h>
#include <math.h>
#include <stdint.h>

// Problem shapes (fixed per reference)
#define N_NODES 20000
#define N_EDGES 40000
#define H 64
#define F_ATOM 62
#define F_BOND 6
#define BGRAPH 512
#define HH 4096          // H*H
#define E_PAD 40064      // 313 * 128, padded edge count for 128-row MMA tiles

// ---------------- scratch (device globals; no allocs allowed) ----------------
__device__ float g_h[N_NODES * H];                    // node state (fp32)
__device__ float g_msg[N_NODES * H];                  // per-step message accumulator
__device__ float g_act[N_NODES * H];                  // atom activation
__device__ __nv_bfloat16 g_mlpb[E_PAD * H];           // edge MLP features (bf16)
__device__ __nv_bfloat16 g_EwB[HH * H];               // B operand: EwB[n=j*64+i][m] = Ew[m][i*64+j]
__device__ __nv_bfloat16 g_Abf[(size_t)E_PAD * HH];   // per-edge matrices, transposed: At[e][j*64+i], bf16
__device__ float g_gsum[BGRAPH * H];                  // graph segment sums

// ---------------- math helpers ----------------
__device__ __forceinline__ float selu_f(float x) {
    const float alpha = 1.6732632423543772f;
    const float scale = 1.0507009873554805f;
    return x > 0.f ? scale * x : scale * alpha * expm1f(x);
}

__device__ __forceinline__ void mma_bf16_16816(float c[4], const uint32_t a[4],
                                               const uint32_t b[2]) {
    asm volatile(
        "mma.sync.aligned.m16n8k16.row.col.f32.bf16.bf16.f32 "
        "{%0,%1,%2,%3}, {%4,%5,%6,%7}, {%8,%9}, {%0,%1,%2,%3};"
        : "+f"(c[0]), "+f"(c[1]), "+f"(c[2]), "+f"(c[3])
        : "r"(a[0]), "r"(a[1]), "r"(a[2]), "r"(a[3]), "r"(b[0]), "r"(b[1]));
}

__global__ void k_zero(float* p, int n) {
    int i = blockIdx.x * blockDim.x + threadIdx.x;
    if (i < n) p[i] = 0.f;
}

// pad node features [N, F_ATOM] -> g_h [N, H]
__global__ void k_pad(const float* __restrict__ nf) {
    int idx = blockIdx.x * blockDim.x + threadIdx.x;
    if (idx >= N_NODES * H) return;
    int n = idx >> 6, c = idx & 63;
    g_h[idx] = (c < F_ATOM) ? nf[n * F_ATOM + c] : 0.f;
}

// mlp = relu(ef @ Wm + bm) -> bf16, padded edges write 0
__global__ void k_mlp(const float* __restrict__ ef, const float* __restrict__ Wm,
                      const float* __restrict__ bm) {
    __shared__ float s_ef[4][F_BOND];
    int tid = threadIdx.x;
    int sub = tid >> 6, i = tid & 63;
    int e = blockIdx.x * 4 + sub;
    if (i < F_BOND) s_ef[sub][i] = (e < N_EDGES) ? ef[e * F_BOND + i] : 0.f;
    __syncthreads();
    float v = bm[i];
#pragma unroll
    for (int f = 0; f < F_BOND; f++) v += s_ef[sub][f] * Wm[f * H + i];
    v = fmaxf(v, 0.f);
    if (e >= N_EDGES) v = 0.f;
    g_mlpb[e * H + i] = __float2bfloat16_rn(v);
}

// build B operand: g_EwB[n=j*64+i][m] = Ew[m][i*64+j]  (bf16)
__global__ void k_buildB(const float* __restrict__ Ew) {
    int o = blockIdx.x * blockDim.x + threadIdx.x;
    if (o >= HH * H) return;
    int n = o >> 6, m = o & 63;
    int j = n >> 6, i = n & 63;
    g_EwB[o] = __float2bfloat16_rn(Ew[(m << 12) + (i << 6) + j]);
}

// A = mlp[E,64] @ EwB^T via mma.sync bf16 (HMMA).
// CTA tile 128x128, K=64 in one shot. 8 warps (2x4): warp tile 64x32.
// smem rows padded to 36 words (144B) -> conflict-free fragment LDS.
#define SROW 36
__global__ void __launch_bounds__(256) k_gemmA_mma() {
    __shared__ __align__(16) uint32_t sA[128 * SROW];
    __shared__ __align__(16) uint32_t sB[128 * SROW];
    int tid = threadIdx.x;
    int m0 = blockIdx.y * 128;   // edge tile
    int n0 = blockIdx.x * 128;   // output-col tile

    // load tiles: 128 rows x 32 words (64 bf16); 8 uint4 chunks per row
    const uint4* gA = (const uint4*)(g_mlpb + (size_t)m0 * H);
    const uint4* gB = (const uint4*)(g_EwB + (size_t)n0 * H);
#pragma unroll
    for (int it = 0; it < 4; it++) {
        int idx = it * 256 + tid;      // 0..1023
        int row = idx >> 3, c = idx & 7;
        *(uint4*)&sA[row * SROW + c * 4] = gA[idx];
        *(uint4*)&sB[row * SROW + c * 4] = gB[idx];
    }
    __syncthreads();

    int wid = tid >> 5, lane = tid & 31;
    int g = lane >> 2, tg = lane & 3;
    int wm = (wid & 1) * 64;   // warp M offset in tile
    int wn = (wid >> 1) * 32;  // warp N offset in tile

    float c[4][4][4] = {};
#pragma unroll
    for (int kk = 0; kk < 4; kk++) {   // K-steps of 16
        uint32_t a[4][4], b[4][2];
#pragma unroll
        for (int mi = 0; mi < 4; mi++) {
            int r = wm + mi * 16 + g;
            a[mi][0] = sA[r * SROW + kk * 8 + tg];
            a[mi][1] = sA[(r + 8) * SROW + kk * 8 + tg];
            a[mi][2] = sA[r * SROW + kk * 8 + 4 + tg];
            a[mi][3] = sA[(r + 8) * SROW + kk * 8 + 4 + tg];
        }
#pragma unroll
        for (int ni = 0; ni < 4; ni++) {
            int r = wn + ni * 8 + g;
            b[ni][0] = sB[r * SROW + kk * 8 + tg];
            b[ni][1] = sB[r * SROW + kk * 8 + 4 + tg];
        }
#pragma unroll
        for (int mi = 0; mi < 4; mi++)
#pragma unroll
            for (int ni = 0; ni < 4; ni++)
                mma_bf16_16816(c[mi][ni], a[mi], b[ni]);
    }

    // epilogue: convert fp32 accum -> bf16 pairs, store b32 each
#pragma unroll
    for (int mi = 0; mi < 4; mi++) {
        int row = m0 + wm + mi * 16 + g;
#pragma unroll
        for (int ni = 0; ni < 4; ni++) {
            int col = n0 + wn + ni * 8 + tg * 2;
            __nv_bfloat162 lo = __float22bfloat162_rn(make_float2(c[mi][ni][0], c[mi][ni][1]));
            __nv_bfloat162 hi = __float22bfloat162_rn(make_float2(c[mi][ni][2], c[mi][ni][3]));
            *(uint32_t*)(g_Abf + (size_t)row * HH + col) = *(uint32_t*)&lo;
            *(uint32_t*)(g_Abf + (size_t)(row + 8) * HH + col) = *(uint32_t*)&hi;
        }
    }
}

// edge pass: 8 edges per 256-thread block, 32 threads/edge, bf16x2 vector loads.
// em[e,i] = sum_j At[e, j*64+i] * h[rng[e], j];  atomicAdd into msg[dom[e], i]
__global__ void __launch_bounds__(256) k_edge(const int* __restrict__ dom,
                                              const int* __restrict__ rng) {
    __shared__ float s_hj[8][64];
    int tid = threadIdx.x;
    int sub = tid >> 5, lane = tid & 31;
    int e = blockIdx.x * 8 + sub;
    int r = rng[e];
    float2 hv = *(const float2*)(g_h + r * H + 2 * lane);
    s_hj[sub][2 * lane] = hv.x;
    s_hj[sub][2 * lane + 1] = hv.y;
    __syncthreads();
    const __nv_bfloat162* Ae = (const __nv_bfloat162*)(g_Abf + (size_t)e * HH);
    float acc0 = 0.f, acc1 = 0.f;
#pragma unroll 8
    for (int j = 0; j < 64; j++) {
        __nv_bfloat162 a2 = __ldg(&Ae[j * 32 + lane]);
        float2 f = __bfloat1622float2(a2);
        float hjv = s_hj[sub][j];
        acc0 = fmaf(f.x, hjv, acc0);
        acc1 = fmaf(f.y, hjv, acc1);
    }
    int d = dom[e];
    atomicAdd(&g_msg[d * H + 2 * lane], acc0);
    atomicAdd(&g_msg[d * H + 2 * lane + 1], acc1);
}

// h = selu(msg @ Wu + bu + h); also resets msg to 0 for the next step/replay
__global__ void k_update(const float* __restrict__ Wu, const float* __restrict__ bu) {
    __shared__ float s_m[4][64];
    int tid = threadIdx.x;
    int sub = tid >> 6, i = tid & 63;
    int n = blockIdx.x * 4 + sub;
    int idx = n * H + i;
    s_m[sub][i] = g_msg[idx];
    g_msg[idx] = 0.f;
    __syncthreads();
    float acc = bu[i];
#pragma unroll 8
    for (int k = 0; k < 64; k++) acc = fmaf(s_m[sub][k], Wu[k * H + i], acc);
    g_h[idx] = selu_f(acc + g_h[idx]);
}

// act = selu((h @ Wae + bae) @ WR + bR)
__global__ void k_embed(const float* __restrict__ Wae, const float* __restrict__ bae,
                        const float* __restrict__ WR, const float* __restrict__ bR) {
    __shared__ float s_h[4][64];
    __shared__ float s_ae[4][64];
    int tid = threadIdx.x;
    int sub = tid >> 6, i = tid & 63;
    int n = blockIdx.x * 4 + sub;
    s_h[sub][i] = g_h[n * H + i];
    __syncthreads();
    float ae = bae[i];
#pragma unroll 8
    for (int k = 0; k < 64; k++) ae = fmaf(s_h[sub][k], Wae[k * H + i], ae);
    s_ae[sub][i] = ae;
    __syncthreads();
    float acc = bR[i];
#pragma unroll 8
    for (int k = 0; k < 64; k++) acc = fmaf(s_ae[sub][k], WR[k * H + i], acc);
    g_act[n * H + i] = selu_f(acc);
}

// segment-sum act over graph_id
__global__ void k_graphsum(const int* __restrict__ gid) {
    int idx = blockIdx.x * blockDim.x + threadIdx.x;
    if (idx >= N_NODES * H) return;
    int n = idx >> 6, i = idx & 63;
    atomicAdd(&g_gsum[gid[n] * H + i], g_act[idx]);
}

// out[b] = relu(tanh(gsum[b]) @ Wmlp + bmlp) @ Wout + bout
__global__ void k_readout(const float* __restrict__ Wmlp, const float* __restrict__ bmlp,
                          const float* __restrict__ Wout, const float* __restrict__ bout,
                          float* __restrict__ out) {
    __shared__ float s_ge[64];
    __shared__ float s_red[64];
    int b = blockIdx.x, i = threadIdx.x;
    s_ge[i] = tanhf(g_gsum[b * H + i]);
    __syncthreads();
    float acc = bmlp[i];
#pragma unroll 8
    for (int k = 0; k < 64; k++) acc = fmaf(s_ge[k], Wmlp[k * H + i], acc);
    float p = fmaxf(acc, 0.f) * Wout[i];
    s_red[i] = p;
    __syncthreads();
#pragma unroll
    for (int s = 32; s > 0; s >>= 1) {
        if (i < s) s_red[i] += s_red[i + s];
        __syncthreads();
    }
    if (i == 0) out[b] = s_red[0] + bout[0];
}

extern "C" void kernel_launch(void* const* d_in, const int* in_sizes, int n_in,
                              void* d_out, int out_size) {
    const float* node_features = (const float*)d_in[0];
    const float* edge_features = (const float*)d_in[1];
    const int*   edge_domain   = (const int*)d_in[2];
    const int*   edge_range    = (const int*)d_in[3];
    const int*   graph_id      = (const int*)d_in[4];
    const float* Wm   = (const float*)d_in[5];
    const float* bm   = (const float*)d_in[6];
    const float* Ew   = (const float*)d_in[7];
    const float* Wu0  = (const float*)d_in[8];
    const float* bu0  = (const float*)d_in[9];
    const float* Wu1  = (const float*)d_in[10];
    const float* bu1  = (const float*)d_in[11];
    const float* Wae  = (const float*)d_in[12];
    const float* bae  = (const float*)d_in[13];
    const float* WR   = (const float*)d_in[14];
    const float* bR   = (const float*)d_in[15];
    const float* Wmlp = (const float*)d_in[16];
    const float* bmlp = (const float*)d_in[17];
    const float* Wout = (const float*)d_in[18];
    const float* bout = (const float*)d_in[19];
    float* out = (float*)d_out;

    // prep
    k_pad<<<(N_NODES * H + 255) / 256, 256>>>(node_features);
    k_mlp<<<E_PAD / 4, 256>>>(edge_features, Wm, bm);
    k_buildB<<<(HH * H + 255) / 256, 256>>>(Ew);

    // A = mlp @ EwB^T on tensor cores (bf16 HMMA, fp32 accumulate, bf16 out)
    dim3 gA(HH / 128, E_PAD / 128);
    k_gemmA_mma<<<gA, 256>>>();

    // message passing steps
    const float* Wus[2] = {Wu0, Wu1};
    const float* bus[2] = {bu0, bu1};
    float* msg_ptr = nullptr;
    cudaGetSymbolAddress((void**)&msg_ptr, g_msg);
    float* gsum_ptr = nullptr;
    cudaGetSymbolAddress((void**)&gsum_ptr, g_gsum);

    k_zero<<<(N_NODES * H + 255) / 256, 256>>>(msg_ptr, N_NODES * H);
    for (int t = 0; t < 2; t++) {
        k_edge<<<N_EDGES / 8, 256>>>(edge_domain, edge_range);
        k_update<<<N_NODES / 4, 256>>>(Wus[t], bus[t]);  // also re-zeroes g_msg
    }

    // readout
    k_embed<<<N_NODES / 4, 256>>>(Wae, bae, WR, bR);
    k_zero<<<(BGRAPH * H + 255) / 256, 256>>>(gsum_ptr, BGRAPH * H);
    k_graphsum<<<(N_NODES * H + 255) / 256, 256>>>(graph_id);
    k_readout<<<BGRAPH, 64>>>(Wmlp, bmlp, Wout, bout, out);
}

// round 7
// speedup vs baseline: 2.6687x; 1.2036x over previous
#include <cuda_runtime.h>
#include <cuda_bf16.h>
#include <math.h>
#include <stdint.h>

// Problem shapes (fixed per reference)
#define N_NODES 20000
#define N_EDGES 40000
#define H 64
#define F_ATOM 62
#define F_BOND 6
#define BGRAPH 512
#define HH 4096          // H*H
#define E_PAD 40064      // 313 * 128, padded edge count for 128-row MMA tiles

// ---------------- scratch (device globals; no allocs allowed) ----------------
__device__ float g_h[N_NODES * H];                    // node state (fp32)
__device__ float g_msg[N_NODES * H];                  // per-step message accumulator
__device__ float g_act[N_NODES * H];                  // atom activation
__device__ __nv_bfloat16 g_mlpb[E_PAD * H];           // edge MLP features (bf16)
__device__ __nv_bfloat16 g_EwB[HH * H];               // B operand: EwB[n=j*64+i][m] = Ew[m][i*64+j]
__device__ __nv_bfloat16 g_Abf[(size_t)E_PAD * HH];   // per-edge matrices, transposed: At[e][j*64+i], bf16
__device__ float g_gsum[BGRAPH * H];                  // graph segment sums

// ---------------- math helpers ----------------
__device__ __forceinline__ float selu_f(float x) {
    const float alpha = 1.6732632423543772f;
    const float scale = 1.0507009873554805f;
    return x > 0.f ? scale * x : scale * alpha * expm1f(x);
}

__device__ __forceinline__ void mma_bf16_16816(float c[4], const uint32_t a[4],
                                               const uint32_t b0, const uint32_t b1) {
    asm volatile(
        "mma.sync.aligned.m16n8k16.row.col.f32.bf16.bf16.f32 "
        "{%0,%1,%2,%3}, {%4,%5,%6,%7}, {%8,%9}, {%0,%1,%2,%3};"
        : "+f"(c[0]), "+f"(c[1]), "+f"(c[2]), "+f"(c[3])
        : "r"(a[0]), "r"(a[1]), "r"(a[2]), "r"(a[3]), "r"(b0), "r"(b1));
}

__device__ __forceinline__ void ldsm_x4(uint32_t r[4], uint32_t saddr) {
    asm volatile("ldmatrix.sync.aligned.m8n8.x4.shared.b16 {%0,%1,%2,%3}, [%4];"
                 : "=r"(r[0]), "=r"(r[1]), "=r"(r[2]), "=r"(r[3]) : "r"(saddr));
}

__global__ void k_zero(float* p, int n) {
    int i = blockIdx.x * blockDim.x + threadIdx.x;
    if (i < n) p[i] = 0.f;
}

// pad node features [N, F_ATOM] -> g_h [N, H]
__global__ void k_pad(const float* __restrict__ nf) {
    int idx = blockIdx.x * blockDim.x + threadIdx.x;
    if (idx >= N_NODES * H) return;
    int n = idx >> 6, c = idx & 63;
    g_h[idx] = (c < F_ATOM) ? nf[n * F_ATOM + c] : 0.f;
}

// mlp = relu(ef @ Wm + bm) -> bf16, padded edges write 0
__global__ void k_mlp(const float* __restrict__ ef, const float* __restrict__ Wm,
                      const float* __restrict__ bm) {
    __shared__ float s_ef[4][F_BOND];
    int tid = threadIdx.x;
    int sub = tid >> 6, i = tid & 63;
    int e = blockIdx.x * 4 + sub;
    if (i < F_BOND) s_ef[sub][i] = (e < N_EDGES) ? ef[e * F_BOND + i] : 0.f;
    __syncthreads();
    float v = bm[i];
#pragma unroll
    for (int f = 0; f < F_BOND; f++) v += s_ef[sub][f] * Wm[f * H + i];
    v = fmaxf(v, 0.f);
    if (e >= N_EDGES) v = 0.f;
    g_mlpb[e * H + i] = __float2bfloat16_rn(v);
}

// build B operand: g_EwB[n=j*64+i][m] = Ew[m][i*64+j]  (bf16)
__global__ void k_buildB(const float* __restrict__ Ew) {
    int o = blockIdx.x * blockDim.x + threadIdx.x;
    if (o >= HH * H) return;
    int n = o >> 6, m = o & 63;
    int j = n >> 6, i = n & 63;
    g_EwB[o] = __float2bfloat16_rn(Ew[(m << 12) + (i << 6) + j]);
}

// A = mlp[E,64] @ EwB^T via mma.sync bf16 (HMMA) with ldmatrix fragment loads
// and a smem-staged fully-coalesced epilogue.
// CTA tile 128x128, K=64. 8 warps (2x4): warp tile 64x32.
#define SROW 36   // padded row (u32 words); 144B = 9*16B -> 16B-aligned rows
#define CROW 68   // staged-C row (u32 words); 272B = 17*16B -> 16B-aligned rows
// one buffer, two phases: phase1 sA(128*SROW) + sB(128*SROW) = 9216 words;
// phase2 sC(128*CROW) = 8704 words (fits in the same 9216).
__global__ void __launch_bounds__(256) k_gemmA_mma() {
    __shared__ __align__(16) uint32_t smem_all[2 * 128 * SROW];  // 36 KB
    uint32_t* sA = smem_all;
    uint32_t* sB = smem_all + 128 * SROW;
    int tid = threadIdx.x;
    int m0 = blockIdx.y * 128;   // edge tile
    int n0 = blockIdx.x * 128;   // output-col tile

    // load tiles: 128 rows x 32 words (64 bf16); 8 uint4 chunks per row
    const uint4* gA = (const uint4*)(g_mlpb + (size_t)m0 * H);
    const uint4* gB = (const uint4*)(g_EwB + (size_t)n0 * H);
#pragma unroll
    for (int it = 0; it < 4; it++) {
        int idx = it * 256 + tid;      // 0..1023
        int row = idx >> 3, c = idx & 7;
        *(uint4*)&sA[row * SROW + c * 4] = gA[idx];
        *(uint4*)&sB[row * SROW + c * 4] = gB[idx];
    }
    __syncthreads();

    int wid = tid >> 5, lane = tid & 31;
    int g = lane >> 2, tg = lane & 3;
    int wm = (wid & 1) * 64;   // warp M offset in tile
    int wn = (wid >> 1) * 32;  // warp N offset in tile

    // ldmatrix lane addressing: row = base + (l&7) + ((l>>3)&1)*8, col-quad = (l>>4)*4
    int lrow = (lane & 7) + ((lane >> 3) & 1) * 8;
    int lcol = (lane >> 4) * 4;

    uint32_t sA_u32 = (uint32_t)__cvta_generic_to_shared(sA);
    uint32_t sB_u32 = (uint32_t)__cvta_generic_to_shared(sB);

    float c[4][4][4] = {};
#pragma unroll
    for (int kk = 0; kk < 4; kk++) {   // K-steps of 16
        uint32_t a[4][4];
#pragma unroll
        for (int mi = 0; mi < 4; mi++) {
            uint32_t addr = sA_u32 + ((wm + mi * 16 + lrow) * SROW + kk * 8 + lcol) * 4;
            ldsm_x4(a[mi], addr);
        }
        uint32_t bq[2][4];
#pragma unroll
        for (int nh = 0; nh < 2; nh++) {
            uint32_t addr = sB_u32 + ((wn + nh * 16 + lrow) * SROW + kk * 8 + lcol) * 4;
            ldsm_x4(bq[nh], addr);
        }
#pragma unroll
        for (int mi = 0; mi < 4; mi++) {
            mma_bf16_16816(c[mi][0], a[mi], bq[0][0], bq[0][2]);
            mma_bf16_16816(c[mi][1], a[mi], bq[0][1], bq[0][3]);
            mma_bf16_16816(c[mi][2], a[mi], bq[1][0], bq[1][2]);
            mma_bf16_16816(c[mi][3], a[mi], bq[1][1], bq[1][3]);
        }
    }

    // stage C in smem (bf16 pairs), then write fully-coalesced rows
    __syncthreads();   // done reading sA/sB
    uint32_t* sC = smem_all;   // [128][CROW] u32; cols 0..63 used (128 bf16)
#pragma unroll
    for (int mi = 0; mi < 4; mi++) {
        int r0 = wm + mi * 16 + g;
#pragma unroll
        for (int ni = 0; ni < 4; ni++) {
            int cw = (wn >> 1) + ni * 4 + tg;   // u32 col index
            __nv_bfloat162 lo = __float22bfloat162_rn(make_float2(c[mi][ni][0], c[mi][ni][1]));
            __nv_bfloat162 hi = __float22bfloat162_rn(make_float2(c[mi][ni][2], c[mi][ni][3]));
            sC[r0 * CROW + cw] = *(uint32_t*)&lo;
            sC[(r0 + 8) * CROW + cw] = *(uint32_t*)&hi;
        }
    }
    __syncthreads();

    // write-out: each instruction covers 2 full rows x 256B contiguous
    int half = lane >> 4;       // 0/1
    int seg = lane & 15;        // 16B segment within row
#pragma unroll
    for (int r = 0; r < 8; r++) {
        int row = wid * 16 + 2 * r + half;
        uint4 v = *(uint4*)&sC[row * CROW + seg * 4];
        *(uint4*)(g_Abf + (size_t)(m0 + row) * HH + n0 + seg * 8) = v;
    }
}

// edge pass: 8 edges per 256-thread block, 32 threads/edge, streaming bf16x2 loads.
// em[e,i] = sum_j At[e, j*64+i] * h[rng[e], j];  atomicAdd into msg[dom[e], i]
__global__ void __launch_bounds__(256) k_edge(const int* __restrict__ dom,
                                              const int* __restrict__ rng) {
    __shared__ float s_hj[8][64];
    int tid = threadIdx.x;
    int sub = tid >> 5, lane = tid & 31;
    int e = blockIdx.x * 8 + sub;
    int r = rng[e];
    float2 hv = *(const float2*)(g_h + r * H + 2 * lane);
    s_hj[sub][2 * lane] = hv.x;
    s_hj[sub][2 * lane + 1] = hv.y;
    __syncthreads();
    const unsigned int* Ae = (const unsigned int*)(g_Abf + (size_t)e * HH);
    float acc0 = 0.f, acc1 = 0.f;
#pragma unroll 8
    for (int j = 0; j < 64; j++) {
        unsigned int raw = __ldcs(&Ae[j * 32 + lane]);   // evict-first: A is stream-once
        __nv_bfloat162 a2 = *reinterpret_cast<__nv_bfloat162*>(&raw);
        float2 f = __bfloat1622float2(a2);
        float hjv = s_hj[sub][j];
        acc0 = fmaf(f.x, hjv, acc0);
        acc1 = fmaf(f.y, hjv, acc1);
    }
    int d = dom[e];
    atomicAdd(&g_msg[d * H + 2 * lane], acc0);
    atomicAdd(&g_msg[d * H + 2 * lane + 1], acc1);
}

// h = selu(msg @ Wu + bu + h); also resets msg to 0 for the next step/replay
__global__ void k_update(const float* __restrict__ Wu, const float* __restrict__ bu) {
    __shared__ float s_m[4][64];
    int tid = threadIdx.x;
    int sub = tid >> 6, i = tid & 63;
    int n = blockIdx.x * 4 + sub;
    int idx = n * H + i;
    s_m[sub][i] = g_msg[idx];
    g_msg[idx] = 0.f;
    __syncthreads();
    float acc = bu[i];
#pragma unroll 8
    for (int k = 0; k < 64; k++) acc = fmaf(s_m[sub][k], Wu[k * H + i], acc);
    g_h[idx] = selu_f(acc + g_h[idx]);
}

// act = selu((h @ Wae + bae) @ WR + bR)
__global__ void k_embed(const float* __restrict__ Wae, const float* __restrict__ bae,
                        const float* __restrict__ WR, const float* __restrict__ bR) {
    __shared__ float s_h[4][64];
    __shared__ float s_ae[4][64];
    int tid = threadIdx.x;
    int sub = tid >> 6, i = tid & 63;
    int n = blockIdx.x * 4 + sub;
    s_h[sub][i] = g_h[n * H + i];
    __syncthreads();
    float ae = bae[i];
#pragma unroll 8
    for (int k = 0; k < 64; k++) ae = fmaf(s_h[sub][k], Wae[k * H + i], ae);
    s_ae[sub][i] = ae;
    __syncthreads();
    float acc = bR[i];
#pragma unroll 8
    for (int k = 0; k < 64; k++) acc = fmaf(s_ae[sub][k], WR[k * H + i], acc);
    g_act[n * H + i] = selu_f(acc);
}

// segment-sum act over graph_id
__global__ void k_graphsum(const int* __restrict__ gid) {
    int idx = blockIdx.x * blockDim.x + threadIdx.x;
    if (idx >= N_NODES * H) return;
    int n = idx >> 6, i = idx & 63;
    atomicAdd(&g_gsum[gid[n] * H + i], g_act[idx]);
}

// out[b] = relu(tanh(gsum[b]) @ Wmlp + bmlp) @ Wout + bout
__global__ void k_readout(const float* __restrict__ Wmlp, const float* __restrict__ bmlp,
                          const float* __restrict__ Wout, const float* __restrict__ bout,
                          float* __restrict__ out) {
    __shared__ float s_ge[64];
    __shared__ float s_red[64];
    int b = blockIdx.x, i = threadIdx.x;
    s_ge[i] = tanhf(g_gsum[b * H + i]);
    __syncthreads();
    float acc = bmlp[i];
#pragma unroll 8
    for (int k = 0; k < 64; k++) acc = fmaf(s_ge[k], Wmlp[k * H + i], acc);
    float p = fmaxf(acc, 0.f) * Wout[i];
    s_red[i] = p;
    __syncthreads();
#pragma unroll
    for (int s = 32; s > 0; s >>= 1) {
        if (i < s) s_red[i] += s_red[i + s];
        __syncthreads();
    }
    if (i == 0) out[b] = s_red[0] + bout[0];
}

extern "C" void kernel_launch(void* const* d_in, const int* in_sizes, int n_in,
                              void* d_out, int out_size) {
    const float* node_features = (const float*)d_in[0];
    const float* edge_features = (const float*)d_in[1];
    const int*   edge_domain   = (const int*)d_in[2];
    const int*   edge_range    = (const int*)d_in[3];
    const int*   graph_id      = (const int*)d_in[4];
    const float* Wm   = (const float*)d_in[5];
    const float* bm   = (const float*)d_in[6];
    const float* Ew   = (const float*)d_in[7];
    const float* Wu0  = (const float*)d_in[8];
    const float* bu0  = (const float*)d_in[9];
    const float* Wu1  = (const float*)d_in[10];
    const float* bu1  = (const float*)d_in[11];
    const float* Wae  = (const float*)d_in[12];
    const float* bae  = (const float*)d_in[13];
    const float* WR   = (const float*)d_in[14];
    const float* bR   = (const float*)d_in[15];
    const float* Wmlp = (const float*)d_in[16];
    const float* bmlp = (const float*)d_in[17];
    const float* Wout = (const float*)d_in[18];
    const float* bout = (const float*)d_in[19];
    float* out = (float*)d_out;

    // prep
    k_pad<<<(N_NODES * H + 255) / 256, 256>>>(node_features);
    k_mlp<<<E_PAD / 4, 256>>>(edge_features, Wm, bm);
    k_buildB<<<(HH * H + 255) / 256, 256>>>(Ew);

    // A = mlp @ EwB^T on tensor cores (bf16 HMMA, fp32 accumulate, bf16 out)
    dim3 gA(HH / 128, E_PAD / 128);
    k_gemmA_mma<<<gA, 256>>>();

    // message passing steps
    const float* Wus[2] = {Wu0, Wu1};
    const float* bus[2] = {bu0, bu1};
    float* msg_ptr = nullptr;
    cudaGetSymbolAddress((void**)&msg_ptr, g_msg);
    float* gsum_ptr = nullptr;
    cudaGetSymbolAddress((void**)&gsum_ptr, g_gsum);

    k_zero<<<(N_NODES * H + 255) / 256, 256>>>(msg_ptr, N_NODES * H);
    for (int t = 0; t < 2; t++) {
        k_edge<<<N_EDGES / 8, 256>>>(edge_domain, edge_range);
        k_update<<<N_NODES / 4, 256>>>(Wus[t], bus[t]);  // also re-zeroes g_msg
    }

    // readout
    k_embed<<<N_NODES / 4, 256>>>(Wae, bae, WR, bR);
    k_zero<<<(BGRAPH * H + 255) / 256, 256>>>(gsum_ptr, BGRAPH * H);
    k_graphsum<<<(N_NODES * H + 255) / 256, 256>>>(graph_id);
    k_readout<<<BGRAPH, 64>>>(Wmlp, bmlp, Wout, bout, out);
}